// round 9
// baseline (speedup 1.0000x reference)
#include <cuda_runtime.h>
#include <cuda_fp16.h>
#include <math.h>

#define D 128
#define MAXN 50000
#define MAXE 1700000

// ---------------- static device scratch (alloc-free) ----------------
__device__ __half2 g_h   [MAXN * 64];   // layer input (after relu), fp16
__device__ __half2 g_hwh [MAXN * 64];   // h @ W, fp16
__device__ float   g_esrc[MAXN];
__device__ float   g_edst[MAXN];
__device__ int     g_cnt [MAXN];
__device__ int     g_off [MAXN];
__device__ int     g_cur [MAXN];
__device__ int     g_ssrc[MAXE];
__device__ __half  g_Wt  [128 * 136];   // transposed fp16 W, padded rows (matches smem layout)

// ================= CSR build (once per launch) =================
__global__ void zero_cnt_kernel(int n) {
    int i = blockIdx.x * blockDim.x + threadIdx.x;
    if (i < n) g_cnt[i] = 0;
}

__global__ void hist_kernel(const int* __restrict__ dst, int E) {
    int e = blockIdx.x * blockDim.x + threadIdx.x;
    if (e < E) atomicAdd(&g_cnt[dst[e]], 1);
}

__global__ void __launch_bounds__(1024) scan_kernel(int n) {
    __shared__ int sums[1024];
    int t = threadIdx.x;
    int chunk = (n + 1023) >> 10;
    int b0 = t * chunk, b1 = min(b0 + chunk, n);
    int s = 0;
    for (int i = b0; i < b1; i++) s += g_cnt[i];
    sums[t] = s;
    __syncthreads();
    for (int off = 1; off < 1024; off <<= 1) {
        int v = (t >= off) ? sums[t - off] : 0;
        __syncthreads();
        sums[t] += v;
        __syncthreads();
    }
    int prefix = (t == 0) ? 0 : sums[t - 1];
    for (int i = b0; i < b1; i++) {
        g_off[i] = prefix;
        g_cur[i] = prefix;
        prefix += g_cnt[i];
    }
}

__global__ void scatter_kernel(const int* __restrict__ src,
                               const int* __restrict__ dst, int E) {
    int e = blockIdx.x * blockDim.x + threadIdx.x;
    if (e >= E) return;
    int p = atomicAdd(&g_cur[dst[e]], 1);
    g_ssrc[p] = src[e];
}

// ================= convert x (fp32) -> g_h (fp16), once =================
__global__ void conv_x_kernel(const float* __restrict__ x, int total_h2) {
    int i = blockIdx.x * blockDim.x + threadIdx.x;
    if (i >= total_h2) return;
    float2 v = ((const float2*)x)[i];
    g_h[i] = __floats2half2_rn(v.x, v.y);
}

// ================= convert W (fp32 [k][n]) -> g_Wt (fp16 [n*136+k]), per layer =================
__global__ void conv_w_kernel(const float* __restrict__ W) {
    int idx = blockIdx.x * blockDim.x + threadIdx.x;   // 16384 threads total
    if (idx >= 128 * 128) return;
    int k = idx >> 7, nn = idx & 127;                  // coalesced read of W
    g_Wt[nn * 136 + k] = __float2half(W[idx]);
}

// ================= HMMA GEMM + fused logits =================
// g_hwh = half(g_h @ W); g_esrc/g_edst from fp32 accumulators.
// block: 128 rows, 256 threads. Wt staged smem via uint4 copy (no converts, no conflicts).
__global__ void __launch_bounds__(256) hgemm_kernel(const float* __restrict__ asrc,
                                                    const float* __restrict__ adst,
                                                    int M) {
    __shared__ __half smWt[128 * 136];
    const int tid  = threadIdx.x;
    const int wid  = tid >> 5;
    const int lane = tid & 31;
    const int g    = lane >> 2;
    const int tg   = lane & 3;

    // stage pre-converted Wt: 34816 B = 2176 uint4
    {
        const uint4* srcp = (const uint4*)g_Wt;
        uint4* dstp = (uint4*)smWt;
        for (int i = tid; i < 2176; i += 256) dstp[i] = srcp[i];
    }
    __syncthreads();

    const __half* Ah = (const __half*)g_h;
    const int r0 = blockIdx.x * 128 + wid * 16 + g;
    const int r1 = r0 + 8;
    const bool v0 = r0 < M, v1 = r1 < M;

    float acc[16][4];
#pragma unroll
    for (int nt = 0; nt < 16; nt++)
#pragma unroll
        for (int j = 0; j < 4; j++) acc[nt][j] = 0.0f;

#pragma unroll
    for (int kstep = 0; kstep < 8; kstep++) {
        const int k0 = kstep * 16 + tg * 2;
        unsigned a0 = v0 ? *(const unsigned*)(Ah + (size_t)r0 * 128 + k0)     : 0u;
        unsigned a1 = v1 ? *(const unsigned*)(Ah + (size_t)r1 * 128 + k0)     : 0u;
        unsigned a2 = v0 ? *(const unsigned*)(Ah + (size_t)r0 * 128 + k0 + 8) : 0u;
        unsigned a3 = v1 ? *(const unsigned*)(Ah + (size_t)r1 * 128 + k0 + 8) : 0u;
#pragma unroll
        for (int nt = 0; nt < 16; nt++) {
            int n = nt * 8 + g;
            unsigned b0 = *(const unsigned*)(smWt + n * 136 + k0);
            unsigned b1 = *(const unsigned*)(smWt + n * 136 + k0 + 8);
            asm volatile(
                "mma.sync.aligned.m16n8k16.row.col.f32.f16.f16.f32 "
                "{%0,%1,%2,%3}, {%4,%5,%6,%7}, {%8,%9}, {%0,%1,%2,%3};"
                : "+f"(acc[nt][0]), "+f"(acc[nt][1]), "+f"(acc[nt][2]), "+f"(acc[nt][3])
                : "r"(a0), "r"(a1), "r"(a2), "r"(a3), "r"(b0), "r"(b1));
        }
    }

    // ---- fused logits
    float sls = 0.f, sld = 0.f, shs = 0.f, shd = 0.f;
#pragma unroll
    for (int nt = 0; nt < 16; nt++) {
        float2 avs = ((const float2*)asrc)[nt * 4 + tg];
        float2 avd = ((const float2*)adst)[nt * 4 + tg];
        sls += acc[nt][0] * avs.x + acc[nt][1] * avs.y;
        sld += acc[nt][0] * avd.x + acc[nt][1] * avd.y;
        shs += acc[nt][2] * avs.x + acc[nt][3] * avs.y;
        shd += acc[nt][2] * avd.x + acc[nt][3] * avd.y;
    }
#pragma unroll
    for (int o = 1; o <= 2; o <<= 1) {
        sls += __shfl_xor_sync(0xffffffffu, sls, o);
        sld += __shfl_xor_sync(0xffffffffu, sld, o);
        shs += __shfl_xor_sync(0xffffffffu, shs, o);
        shd += __shfl_xor_sync(0xffffffffu, shd, o);
    }

    if (v0) {
#pragma unroll
        for (int nt = 0; nt < 16; nt++)
            g_hwh[(size_t)r0 * 64 + nt * 4 + tg] = __floats2half2_rn(acc[nt][0], acc[nt][1]);
        if (tg == 0) { g_esrc[r0] = sls; g_edst[r0] = sld; }
    }
    if (v1) {
#pragma unroll
        for (int nt = 0; nt < 16; nt++)
            g_hwh[(size_t)r1 * 64 + nt * 4 + tg] = __floats2half2_rn(acc[nt][2], acc[nt][3]);
        if (tg == 0) { g_esrc[r1] = shs; g_edst[r1] = shd; }
    }
}

// ================= fused GAT: softmax + aggregate + bias + relu =================
// one warp per dst node; atomic-free; 8-deep MLP fp16 gathers; writes g_h (fp16)
__global__ void __launch_bounds__(256) gat_aggregate_kernel(const float* __restrict__ b, int n) {
    int d    = (blockIdx.x * blockDim.x + threadIdx.x) >> 5;
    int lane = threadIdx.x & 31;
    if (d >= n) return;

    const int start = g_off[d];
    const int end   = start + g_cnt[d];
    const float edst_d = g_edst[d];

    float lg_self;
    {
        float x = g_esrc[d] + edst_d;
        lg_self = (x > 0.f) ? x : 0.2f * x;
    }

    // ---- online segment softmax over real edges
    float m_l = -1e30f, s_l = 0.f;
    for (int e = start + lane; e < end; e += 32) {
        int s = g_ssrc[e];
        float x = g_esrc[s] + edst_d;
        float lg = (x > 0.f) ? x : 0.2f * x;
        if (lg > m_l) {
            s_l = fmaf(s_l, __expf(m_l - lg), 1.f);
            m_l = lg;
        } else {
            s_l += __expf(lg - m_l);
        }
    }
#pragma unroll
    for (int o = 16; o > 0; o >>= 1) {
        float m2 = __shfl_xor_sync(0xffffffffu, m_l, o);
        float s2 = __shfl_xor_sync(0xffffffffu, s_l, o);
        float M2 = fmaxf(m_l, m2);
        s_l = s_l * __expf(m_l - M2) + s2 * __expf(m2 - M2);
        m_l = M2;
    }
    const float M   = fmaxf(m_l, lg_self);
    const float den = s_l * __expf(m_l - M) + __expf(lg_self - M);
    const float inv_den = 1.0f / den;

    // ---- self-loop contribution
    float4 acc;
    {
        float a_self = __expf(lg_self - M) * inv_den;
        uint2 u = *(const uint2*)(g_hwh + (size_t)d * 64 + lane * 2);
        float2 fa = __half22float2(*(__half2*)&u.x);
        float2 fb = __half22float2(*(__half2*)&u.y);
        acc.x = fa.x * a_self; acc.y = fa.y * a_self;
        acc.z = fb.x * a_self; acc.w = fb.y * a_self;
    }

    // ---- full 32-edge chunks: 8 independent gathers in flight
    int base = start;
    for (; base + 32 <= end; base += 32) {
        int s = g_ssrc[base + lane];
        float x = g_esrc[s] + edst_d;
        float lg = (x > 0.f) ? x : 0.2f * x;
        float alpha = __expf(lg - M) * inv_den;
#pragma unroll
        for (int j = 0; j < 32; j += 8) {
            float av[8];
            int   sv[8];
            uint2 uv[8];
#pragma unroll
            for (int q = 0; q < 8; q++) {
                av[q] = __shfl_sync(0xffffffffu, alpha, j + q);
                sv[q] = __shfl_sync(0xffffffffu, s, j + q);
            }
#pragma unroll
            for (int q = 0; q < 8; q++)
                uv[q] = *(const uint2*)(g_hwh + (size_t)sv[q] * 64 + lane * 2);
#pragma unroll
            for (int q = 0; q < 8; q++) {
                float2 fa = __half22float2(*(__half2*)&uv[q].x);
                float2 fb = __half22float2(*(__half2*)&uv[q].y);
                acc.x = fmaf(fa.x, av[q], acc.x);
                acc.y = fmaf(fa.y, av[q], acc.y);
                acc.z = fmaf(fb.x, av[q], acc.z);
                acc.w = fmaf(fb.y, av[q], acc.w);
            }
        }
    }
    // ---- tail chunk (< 32 edges)
    if (base < end) {
        int e = base + lane;
        int s = 0;
        float alpha = 0.f;
        if (e < end) {
            s = g_ssrc[e];
            float x = g_esrc[s] + edst_d;
            float lg = (x > 0.f) ? x : 0.2f * x;
            alpha = __expf(lg - M) * inv_den;
        }
        int c = end - base;
        for (int j = 0; j < c; j++) {
            float a  = __shfl_sync(0xffffffffu, alpha, j);
            int   sj = __shfl_sync(0xffffffffu, s, j);
            uint2 u = *(const uint2*)(g_hwh + (size_t)sj * 64 + lane * 2);
            float2 fa = __half22float2(*(__half2*)&u.x);
            float2 fb = __half22float2(*(__half2*)&u.y);
            acc.x = fmaf(fa.x, a, acc.x);
            acc.y = fmaf(fa.y, a, acc.y);
            acc.z = fmaf(fb.x, a, acc.z);
            acc.w = fmaf(fb.y, a, acc.w);
        }
    }

    // ---- bias + relu, store fp16 for next layer
    float4 bb = *(const float4*)(b + lane * 4);
    uint2 o;
    __half2 o0 = __floats2half2_rn(fmaxf(acc.x + bb.x, 0.f), fmaxf(acc.y + bb.y, 0.f));
    __half2 o1 = __floats2half2_rn(fmaxf(acc.z + bb.z, 0.f), fmaxf(acc.w + bb.w, 0.f));
    o.x = *(unsigned*)&o0;
    o.y = *(unsigned*)&o1;
    *(uint2*)(g_h + (size_t)d * 64 + lane * 2) = o;
}

// ================= mean over nodes -> d_out[128] =================
__global__ void zero_out_kernel(float* out) {
    if (threadIdx.x < D) out[threadIdx.x] = 0.0f;
}

__global__ void mean_kernel(float* __restrict__ out, int n) {
    int j  = threadIdx.x;          // column 0..127
    int r0 = blockIdx.x * 128;
    int r1 = min(r0 + 128, n);
    float s = 0.0f;
    for (int r = r0; r < r1; r++) {
        __half2 v = g_h[(size_t)r * 64 + (j >> 1)];
        s += (j & 1) ? __high2float(v) : __low2float(v);
    }
    atomicAdd(&out[j], s * (1.0f / n));
}

// ================= launch (kernel launches only) =================
extern "C" void kernel_launch(void* const* d_in, const int* in_sizes, int n_in,
                              void* d_out, int out_size) {
    const float* x  = (const float*)d_in[0];
    const int*   ei = (const int*)d_in[1];
    const int n = in_sizes[0] / D;
    const int E = in_sizes[1] / 2;
    const int* src = ei;
    const int* dst = ei + E;

    // CSR by dst (graph identical across layers)
    zero_cnt_kernel<<<(n + 255) / 256, 256>>>(n);
    hist_kernel<<<(E + 255) / 256, 256>>>(dst, E);
    scan_kernel<<<1, 1024>>>(n);
    scatter_kernel<<<(E + 255) / 256, 256>>>(src, dst, E);

    // x -> fp16
    conv_x_kernel<<<(n * 64 + 255) / 256, 256>>>(x, n * 64);

    for (int l = 0; l < 3; l++) {
        const float* w    = (const float*)d_in[2 + l * 4 + 0];
        const float* asrc = (const float*)d_in[2 + l * 4 + 1];
        const float* adst = (const float*)d_in[2 + l * 4 + 2];
        const float* b    = (const float*)d_in[2 + l * 4 + 3];

        conv_w_kernel<<<64, 256>>>(w);
        hgemm_kernel<<<(n + 127) / 128, 256>>>(asrc, adst, n);
        gat_aggregate_kernel<<<(n * 32 + 255) / 256, 256>>>(b, n);
    }

    zero_out_kernel<<<1, 128>>>((float*)d_out);
    mean_kernel<<<(n + 127) / 128, 128>>>((float*)d_out, n);
}